// round 9
// baseline (speedup 1.0000x reference)
#include <cuda_runtime.h>

#define NUM_C 19
#define NUM_A 512            // feature channels
#define A4 (NUM_A / 4)       // float4 per row = 128
#define A2 (NUM_A / 2)       // float2 per row = 256
#define GRID1 148            // accum blocks: 1 per SM
#define NFIN  (NUM_C * 8)    // finalize blocks: 152
#define TPB1 1024            // 4 groups of 256 threads (32 warps/SM)
#define CPAD 20              // padded class stride for count buckets

// Per-group replica layout inside dynamic smem:
//   float4 ssum[4][NUM_C * A4]   (155648 B)
//   float  scnt[32][CPAD]        (2560 B)
#define SMEM_SSUM_F4 (4 * NUM_C * A4)
#define SMEM_BYTES   (SMEM_SSUM_F4 * 16 + 32 * CPAD * 4)

// Deterministic partial-sum scratch (no device-side allocation allowed).
__device__ float g_psums[(size_t)GRID1 * NUM_C * NUM_A]; // [g][c][a]  ~5.8 MB
__device__ float g_pcnts[GRID1 * NUM_C];                 // [g][c]
__device__ int   g_done;                                 // accum blocks finished
__device__ int   g_fin;                                  // finalize blocks past gate

// ---- 8-row batch helpers (software pipeline, float2 lanes) ----
#define LOAD_BATCH(RR, LAB, F)                                              \
    do {                                                                    \
        const int4 L0 = __ldg((const int4*)&labels[(RR)]);                  \
        const int4 L1 = __ldg((const int4*)&labels[(RR) + 4]);              \
        LAB[0] = L0.x; LAB[1] = L0.y; LAB[2] = L0.z; LAB[3] = L0.w;         \
        LAB[4] = L1.x; LAB[5] = L1.y; LAB[6] = L1.z; LAB[7] = L1.w;         \
        _Pragma("unroll")                                                   \
        for (int j = 0; j < 8; j++)                                         \
            if (LAB[j] != ign)                                              \
                F[j] = __ldcs(&feat2[(size_t)((RR) + j) * A2 + tt2]);       \
    } while (0)

#define RMW_BATCH(LAB, F)                                                   \
    do {                                                                    \
        _Pragma("unroll")                                                   \
        for (int j = 0; j < 8; j++) {                                       \
            if (LAB[j] != ign) {                                            \
                const int idx = LAB[j] * A2 + tt2;                          \
                float2 s = ssum2[idx];                                      \
                s.x += F[j].x; s.y += F[j].y;                               \
                ssum2[idx] = s;                                             \
            }                                                               \
        }                                                                   \
        if (lane == 0) {                                                    \
            if (LAB[wgw] != ign) scnt[warp * CPAD + LAB[wgw]] += 1.f;       \
        }                                                                   \
    } while (0)

__device__ __forceinline__ void accum_part(
    const float2* __restrict__ feat2,
    const int*    __restrict__ labels,
    const int*    __restrict__ ignore_ptr,
    int N, float4* smem4)
{
    const int t    = threadIdx.x;
    const int grp  = t >> 8;        // group 0..3 (one smem replica each)
    const int tt2  = t & 255;       // float2 channel within group
    const int warp = t >> 5;        // 0..31
    const int wgw  = warp & 7;      // warp within group (0..7)
    const int lane = t & 31;

    float2* ssum2 = (float2*)(smem4 + (size_t)grp * (NUM_C * A4));
    float*  scnt  = (float*)(smem4 + SMEM_SSUM_F4);       // [32][CPAD]

    #pragma unroll
    for (int i = t; i < SMEM_SSUM_F4; i += TPB1)
        smem4[i] = make_float4(0.f, 0.f, 0.f, 0.f);
    if (t < 32 * CPAD) scnt[t] = 0.f;
    __syncthreads();

    const int ign   = *ignore_ptr;
    // rows per block rounded to 32 so group chunks stay 8-aligned (int4 labels)
    const int rowsb = (((N + GRID1 - 1) / GRID1) + 31) & ~31;
    const int r0b   = blockIdx.x * rowsb;
    const int r1b   = min(r0b + rowsb, N);

    const int nb    = max(r1b - r0b, 0);
    int chunk = (nb + 3) >> 2;
    chunk = (chunk + 7) & ~7;                             // 8-aligned
    const int r0    = min(r0b + grp * chunk, r1b);
    const int r1    = min(r0 + chunk, r1b);

    const int nfull = (r1 - r0) >> 3;       // full 8-row batches

    int    labA[8], labB[8];
    float2 fA[8],   fB[8];

    if (nfull > 0) LOAD_BATCH(r0, labA, fA);

    int b = 0;
    // Pipelined main loop: prefetch batch b+1 before consuming batch b.
    for (; b + 2 < nfull; b += 2) {
        LOAD_BATCH(r0 + (b + 1) * 8, labB, fB);
        RMW_BATCH(labA, fA);
        LOAD_BATCH(r0 + (b + 2) * 8, labA, fA);
        RMW_BATCH(labB, fB);
    }
    if (nfull > 0) {
        if (b + 1 < nfull) {
            LOAD_BATCH(r0 + (b + 1) * 8, labB, fB);
            RMW_BATCH(labA, fA);
            RMW_BATCH(labB, fB);
        } else {
            RMW_BATCH(labA, fA);
        }
    }
    // scalar tail
    for (int r = r0 + nfull * 8; r < r1; r++) {
        const int lab = __ldg(&labels[r]);
        if (lab != ign) {
            float2 f = __ldcs(&feat2[(size_t)r * A2 + tt2]);
            const int idx = lab * A2 + tt2;
            float2 s = ssum2[idx];
            s.x += f.x; s.y += f.y;
            ssum2[idx] = s;
            if (tt2 == 0) scnt[(grp * 8) * CPAD + lab] += 1.f;
        }
    }
    __syncthreads();

    // Reduce the 4 group replicas and store one slab per block.
    float4* pout = reinterpret_cast<float4*>(g_psums) + (size_t)blockIdx.x * NUM_C * A4;
    #pragma unroll
    for (int i = t; i < NUM_C * A4; i += TPB1) {
        float4 a  = smem4[i];
        float4 bb = smem4[i + NUM_C * A4];
        float4 c4 = smem4[i + 2 * NUM_C * A4];
        float4 d  = smem4[i + 3 * NUM_C * A4];
        a.x = (a.x + bb.x) + (c4.x + d.x);
        a.y = (a.y + bb.y) + (c4.y + d.y);
        a.z = (a.z + bb.z) + (c4.z + d.z);
        a.w = (a.w + bb.w) + (c4.w + d.w);
        pout[i] = a;
    }
    if (t < NUM_C) {
        float cl = 0.f;
        #pragma unroll
        for (int w = 0; w < 32; w++) cl += scnt[w * CPAD + t];
        g_pcnts[blockIdx.x * NUM_C + t] = cl;
    }
    __syncthreads();
    __threadfence();                       // release psums/pcnts
    if (t == 0) atomicAdd(&g_done, 1);
}

__device__ __forceinline__ void finalize_part(float* __restrict__ out, float4* smem4)
{
    const int fb   = blockIdx.x - GRID1;   // 0..151
    const int c    = fb >> 3;              // class
    const int agrp = fb & 7;               // 16-float4 channel group
    const int t    = threadIdx.x;
    const int a4   = t & 15;    // 0..15
    const int gp   = t >> 4;    // 0..63
    const int warp = t >> 5;    // 0..31
    const int lane = t & 31;

    float4* red = smem4;                   // [64][16]
    __shared__ float wcnt[32];

    // ---- gate: wait for all accum blocks ----
    if (t == 0) {
        while (atomicAdd(&g_done, 0) < GRID1)
            __nanosleep(256);
    }
    __syncthreads();
    __threadfence();                       // acquire psums/pcnts

    const float4* ps = reinterpret_cast<const float4*>(g_psums);
    const size_t stride = (size_t)NUM_C * A4;
    const size_t off    = (size_t)c * A4 + agrp * 16 + a4;

    // ---- per-class count: one load per thread (148 <= 1024), warp-reduced ----
    {
        float cl = (t < GRID1) ? g_pcnts[t * NUM_C + c] : 0.f;
        #pragma unroll
        for (int o = 16; o > 0; o >>= 1)
            cl += __shfl_down_sync(0xFFFFFFFFu, cl, o);
        if (lane == 0) wcnt[warp] = cl;
    }

    // ---- partial-sum reduction: g = gp, gp+64, + pred g = 128+gp (gp<20) ----
    const float4* base = ps + off + (size_t)gp * stride;
    float4 v0 = base[0];
    float4 v1 = base[(size_t)64 * stride];
    float4 v2 = make_float4(0.f, 0.f, 0.f, 0.f);
    if (gp < GRID1 - 128)
        v2 = base[(size_t)128 * stride];

    float4 acc;
    acc.x = (v0.x + v1.x) + v2.x;
    acc.y = (v0.y + v1.y) + v2.y;
    acc.z = (v0.z + v1.z) + v2.z;
    acc.w = (v0.w + v1.w) + v2.w;
    red[gp * 16 + a4] = acc;
    __syncthreads();

    // Fold 64 g-partitions -> 1.
    #pragma unroll
    for (int s = 32; s > 0; s >>= 1) {
        if (gp < s) {
            float4 a = red[gp * 16 + a4];
            float4 b = red[(gp + s) * 16 + a4];
            a.x += b.x; a.y += b.y; a.z += b.z; a.w += b.w;
            red[gp * 16 + a4] = a;
        }
        __syncthreads();
    }

    if (t < 16) {
        float cnt = 0.f;
        #pragma unroll
        for (int w = 0; w < 32; w++) cnt += wcnt[w];
        const float inv = 1.f / ((cnt == 0.f) ? 1.f : cnt);
        float4 sum = red[a4];
        float4 mean = make_float4(sum.x * inv, sum.y * inv, sum.z * inv, sum.w * inv);

        float4* out4 = reinterpret_cast<float4*>(out);
        const int oidx = c * A4 + agrp * 16 + a4;
        out4[oidx] = mean;                                         // mean (C, A)
        out4[NUM_C * A4 + oidx] = make_float4(cnt, cnt, cnt, cnt); // sum_weight
        if (t == 0 && agrp == 0)
            out[2 * NUM_C * NUM_A + c] = cnt;                      // class_dist (C,)
    }

    // ---- counter self-reset so graph replays start from zero ----
    if (t == 0) {
        const int v = atomicAdd(&g_fin, 1);
        if (v == NFIN - 1) {               // all finalize blocks passed the gate
            g_fin  = 0;
            g_done = 0;
            __threadfence();
        }
    }
}

__global__ void __launch_bounds__(TPB1, 1) bars_fused_kernel(
    const float2* __restrict__ feat2,
    const int*    __restrict__ labels,
    const int*    __restrict__ ignore_ptr,
    int N, float* __restrict__ out)
{
    extern __shared__ float4 smem4[];
    if (blockIdx.x < GRID1)
        accum_part(feat2, labels, ignore_ptr, N, smem4);
    else
        finalize_part(out, smem4);
}

extern "C" void kernel_launch(void* const* d_in, const int* in_sizes, int n_in,
                              void* d_out, int out_size)
{
    const float2* feat2  = (const float2*)d_in[0];
    const int*    labels = (const int*)d_in[1];
    const int*    ign    = (const int*)d_in[2];
    float*        out    = (float*)d_out;

    const int N = in_sizes[0] / NUM_A;

    cudaFuncSetAttribute(bars_fused_kernel,
                         cudaFuncAttributeMaxDynamicSharedMemorySize, SMEM_BYTES);

    bars_fused_kernel<<<GRID1 + NFIN, TPB1, SMEM_BYTES>>>(feat2, labels, ign, N, out);
}

// round 10
// speedup vs baseline: 1.0825x; 1.0825x over previous
#include <cuda_runtime.h>

#define NUM_C 19
#define NUM_A 512            // feature channels
#define A4 (NUM_A / 4)       // float4 per row = 128
#define GRID1 148            // accum blocks: 1 per SM
#define NFIN  (NUM_C * 8)    // finalize blocks: 152
#define TPB1 640             // 5 warpgroups of 128 threads (20 warps/SM)
#define NGRP 5
#define CPAD 20              // padded class stride for count buckets

// Per-warpgroup replica layout inside dynamic smem:
//   float4 ssum[5][NUM_C * A4]   (194560 B)
//   float  scnt[20][CPAD]        (1600 B)
#define SMEM_SSUM_F4 (NGRP * NUM_C * A4)
#define SMEM_BYTES   (SMEM_SSUM_F4 * 16 + 20 * CPAD * 4)

// Deterministic partial-sum scratch (no device-side allocation allowed).
__device__ float g_psums[(size_t)GRID1 * NUM_C * NUM_A]; // [g][c][a]  ~5.8 MB
__device__ float g_pcnts[GRID1 * NUM_C];                 // [g][c]
__device__ int   g_done;                                 // accum blocks finished
__device__ int   g_fin;                                  // finalize blocks past gate

// ---- 8-row batch helpers (software pipeline, float4 lanes) ----
#define LOAD_BATCH(RR, LAB, F)                                              \
    do {                                                                    \
        const int4 L0 = __ldg((const int4*)&labels[(RR)]);                  \
        const int4 L1 = __ldg((const int4*)&labels[(RR) + 4]);              \
        LAB[0] = L0.x; LAB[1] = L0.y; LAB[2] = L0.z; LAB[3] = L0.w;         \
        LAB[4] = L1.x; LAB[5] = L1.y; LAB[6] = L1.z; LAB[7] = L1.w;         \
        _Pragma("unroll")                                                   \
        for (int j = 0; j < 8; j++)                                         \
            if (LAB[j] != ign)                                              \
                F[j] = __ldcs(&feat[(size_t)((RR) + j) * A4 + tt]);         \
    } while (0)

#define RMW_BATCH(LAB, F)                                                   \
    do {                                                                    \
        _Pragma("unroll")                                                   \
        for (int j = 0; j < 8; j++) {                                       \
            if (LAB[j] != ign) {                                            \
                const int idx = LAB[j] * A4 + tt;                           \
                float4 s = ssum[idx];                                       \
                s.x += F[j].x; s.y += F[j].y; s.z += F[j].z; s.w += F[j].w; \
                ssum[idx] = s;                                              \
            }                                                               \
        }                                                                   \
        if (lane == 0) {                                                    \
            _Pragma("unroll")                                               \
            for (int j = 0; j < 2; j++) {                                   \
                const int jj = wgw * 2 + j;                                 \
                if (LAB[jj] != ign) scnt[warp * CPAD + LAB[jj]] += 1.f;     \
            }                                                               \
        }                                                                   \
    } while (0)

__device__ __forceinline__ void accum_part(
    const float4* __restrict__ feat,
    const int*    __restrict__ labels,
    const int*    __restrict__ ignore_ptr,
    int N, float4* smem4)
{
    const int t    = threadIdx.x;
    const int wg   = t >> 7;        // warpgroup 0..4
    const int tt   = t & 127;       // float4 channel within warpgroup
    const int warp = t >> 5;        // 0..19
    const int wgw  = warp & 3;      // warp within warpgroup
    const int lane = t & 31;

    float4* ssum = smem4 + (size_t)wg * (NUM_C * A4);     // this wg's replica
    float*  scnt = (float*)(smem4 + SMEM_SSUM_F4);        // [20][CPAD]

    for (int i = t; i < SMEM_SSUM_F4; i += TPB1)
        smem4[i] = make_float4(0.f, 0.f, 0.f, 0.f);
    if (t < 20 * CPAD) scnt[t] = 0.f;
    __syncthreads();

    const int ign   = *ignore_ptr;
    // rows per block rounded to 40 so warpgroup chunks stay 8-aligned
    const int rowsb = (((N + GRID1 - 1) / GRID1) + 39) / 40 * 40;
    const int r0b   = blockIdx.x * rowsb;
    const int r1b   = min(r0b + rowsb, N);

    const int nb    = max(r1b - r0b, 0);
    int chunk = (nb + NGRP - 1) / NGRP;
    chunk = (chunk + 7) & ~7;                             // 8-aligned
    const int r0    = min(r0b + wg * chunk, r1b);
    const int r1    = min(r0 + chunk, r1b);

    const int nfull = (r1 - r0) >> 3;       // full 8-row batches

    int    labA[8], labB[8];
    float4 fA[8],   fB[8];

    if (nfull > 0) LOAD_BATCH(r0, labA, fA);

    int b = 0;
    // Pipelined main loop: prefetch batch b+1 before consuming batch b.
    for (; b + 2 < nfull; b += 2) {
        LOAD_BATCH(r0 + (b + 1) * 8, labB, fB);
        RMW_BATCH(labA, fA);
        LOAD_BATCH(r0 + (b + 2) * 8, labA, fA);
        RMW_BATCH(labB, fB);
    }
    if (nfull > 0) {
        if (b + 1 < nfull) {
            LOAD_BATCH(r0 + (b + 1) * 8, labB, fB);
            RMW_BATCH(labA, fA);
            RMW_BATCH(labB, fB);
        } else {
            RMW_BATCH(labA, fA);
        }
    }
    // scalar tail
    for (int r = r0 + nfull * 8; r < r1; r++) {
        const int lab = __ldg(&labels[r]);
        if (lab != ign) {
            float4 f = __ldcs(&feat[(size_t)r * A4 + tt]);
            const int idx = lab * A4 + tt;
            float4 s = ssum[idx];
            s.x += f.x; s.y += f.y; s.z += f.z; s.w += f.w;
            ssum[idx] = s;
            if (tt == 0) scnt[(wg * 4) * CPAD + lab] += 1.f;
        }
    }
    __syncthreads();

    // Reduce the 5 warpgroup replicas and store one slab per block.
    float4* pout = reinterpret_cast<float4*>(g_psums) + (size_t)blockIdx.x * NUM_C * A4;
    for (int i = t; i < NUM_C * A4; i += TPB1) {
        float4 a  = smem4[i];
        float4 b1 = smem4[i + NUM_C * A4];
        float4 b2 = smem4[i + 2 * NUM_C * A4];
        float4 b3 = smem4[i + 3 * NUM_C * A4];
        float4 b4 = smem4[i + 4 * NUM_C * A4];
        a.x = ((a.x + b1.x) + (b2.x + b3.x)) + b4.x;
        a.y = ((a.y + b1.y) + (b2.y + b3.y)) + b4.y;
        a.z = ((a.z + b1.z) + (b2.z + b3.z)) + b4.z;
        a.w = ((a.w + b1.w) + (b2.w + b3.w)) + b4.w;
        pout[i] = a;
    }
    if (t < NUM_C) {
        float cl = 0.f;
        #pragma unroll
        for (int w = 0; w < 20; w++) cl += scnt[w * CPAD + t];
        g_pcnts[blockIdx.x * NUM_C + t] = cl;
    }
    __syncthreads();
    __threadfence();                       // release psums/pcnts
    if (t == 0) atomicAdd(&g_done, 1);
}

__device__ __forceinline__ void finalize_part(float* __restrict__ out, float4* smem4)
{
    const int fb   = blockIdx.x - GRID1;   // 0..151
    const int c    = fb >> 3;              // class
    const int agrp = fb & 7;               // 16-float4 channel group
    const int t    = threadIdx.x;
    const int a4   = t & 15;    // 0..15
    const int gp   = t >> 4;    // 0..39 (only gp<32 used for loads)
    const int warp = t >> 5;    // 0..19
    const int lane = t & 31;

    float4* red = smem4;                   // [32][16]
    __shared__ float wcnt[20];

    // ---- gate: wait for all accum blocks ----
    if (t == 0) {
        while (atomicAdd(&g_done, 0) < GRID1)
            __nanosleep(256);
    }
    __syncthreads();
    __threadfence();                       // acquire psums/pcnts

    const float4* ps = reinterpret_cast<const float4*>(g_psums);
    const size_t stride = (size_t)NUM_C * A4;
    const size_t off    = (size_t)c * A4 + agrp * 16 + a4;

    // ---- per-class count: one load per thread (148 <= 640), warp-reduced ----
    {
        float cl = (t < GRID1) ? g_pcnts[t * NUM_C + c] : 0.f;
        #pragma unroll
        for (int o = 16; o > 0; o >>= 1)
            cl += __shfl_down_sync(0xFFFFFFFFu, cl, o);
        if (lane == 0) wcnt[warp] = cl;
    }

    // ---- partial-sum reduction (threads 0..511): g = gp + 32k + pred ----
    if (t < 512) {
        const float4* base = ps + off + (size_t)gp * stride;
        float4 v0 = base[0];
        float4 v1 = base[(size_t)32 * stride];
        float4 v2 = base[(size_t)64 * stride];
        float4 v3 = base[(size_t)96 * stride];
        float4 v4 = make_float4(0.f, 0.f, 0.f, 0.f);
        if (gp < GRID1 - 128)
            v4 = base[(size_t)128 * stride];

        float4 acc;
        acc.x = (v0.x + v1.x) + (v2.x + v3.x) + v4.x;
        acc.y = (v0.y + v1.y) + (v2.y + v3.y) + v4.y;
        acc.z = (v0.z + v1.z) + (v2.z + v3.z) + v4.z;
        acc.w = (v0.w + v1.w) + (v2.w + v3.w) + v4.w;
        red[gp * 16 + a4] = acc;
    }
    __syncthreads();

    // Fold 32 g-partitions -> 1.
    #pragma unroll
    for (int s = 16; s > 0; s >>= 1) {
        if (t < 512 && gp < s) {
            float4 a = red[gp * 16 + a4];
            float4 b = red[(gp + s) * 16 + a4];
            a.x += b.x; a.y += b.y; a.z += b.z; a.w += b.w;
            red[gp * 16 + a4] = a;
        }
        __syncthreads();
    }

    if (t < 16) {
        float cnt = 0.f;
        #pragma unroll
        for (int w = 0; w < 20; w++) cnt += wcnt[w];
        const float inv = 1.f / ((cnt == 0.f) ? 1.f : cnt);
        float4 sum = red[a4];
        float4 mean = make_float4(sum.x * inv, sum.y * inv, sum.z * inv, sum.w * inv);

        float4* out4 = reinterpret_cast<float4*>(out);
        const int oidx = c * A4 + agrp * 16 + a4;
        out4[oidx] = mean;                                         // mean (C, A)
        out4[NUM_C * A4 + oidx] = make_float4(cnt, cnt, cnt, cnt); // sum_weight
        if (t == 0 && agrp == 0)
            out[2 * NUM_C * NUM_A + c] = cnt;                      // class_dist (C,)
    }

    // ---- counter self-reset so graph replays start from zero ----
    if (t == 0) {
        const int v = atomicAdd(&g_fin, 1);
        if (v == NFIN - 1) {               // all finalize blocks passed the gate
            g_fin  = 0;
            g_done = 0;
            __threadfence();
        }
    }
}

__global__ void __launch_bounds__(TPB1, 1) bars_fused_kernel(
    const float4* __restrict__ feat,
    const int*    __restrict__ labels,
    const int*    __restrict__ ignore_ptr,
    int N, float* __restrict__ out)
{
    extern __shared__ float4 smem4[];
    if (blockIdx.x < GRID1)
        accum_part(feat, labels, ignore_ptr, N, smem4);
    else
        finalize_part(out, smem4);
}

extern "C" void kernel_launch(void* const* d_in, const int* in_sizes, int n_in,
                              void* d_out, int out_size)
{
    const float4* feat   = (const float4*)d_in[0];
    const int*    labels = (const int*)d_in[1];
    const int*    ign    = (const int*)d_in[2];
    float*        out    = (float*)d_out;

    const int N = in_sizes[0] / NUM_A;

    cudaFuncSetAttribute(bars_fused_kernel,
                         cudaFuncAttributeMaxDynamicSharedMemorySize, SMEM_BYTES);

    bars_fused_kernel<<<GRID1 + NFIN, TPB1, SMEM_BYTES>>>(feat, labels, ign, N, out);
}

// round 11
// speedup vs baseline: 1.1043x; 1.0201x over previous
#include <cuda_runtime.h>

#define NUM_C 19
#define NUM_A 512            // feature channels
#define A4 (NUM_A / 4)       // float4 per row = 128
#define GRID1 148            // 1 block per SM, single wave (all co-resident)
#define NUNITS (NUM_C * 8)   // 152 finalize units
#define TPB1 512             // 4 warpgroups of 128 threads
#define CPAD 20              // padded class stride for count buckets

// Per-warpgroup replica layout inside dynamic smem:
//   float4 ssum[4][NUM_C * A4]   (155648 B)
//   float  scnt[16][CPAD]        (1280 B)
#define SMEM_SSUM_F4 (4 * NUM_C * A4)
#define SMEM_BYTES   (SMEM_SSUM_F4 * 16 + 16 * CPAD * 4)

// Deterministic partial-sum scratch (no device-side allocation allowed).
__device__ float g_psums[(size_t)GRID1 * NUM_C * NUM_A]; // [g][c][a]  ~5.8 MB
__device__ float g_pcnts[GRID1 * NUM_C];                 // [g][c]
__device__ int   g_done;                                 // accum blocks finished
__device__ int   g_fin;                                  // blocks finished finalize

// ---- 8-row batch helpers (software pipeline) ----
#define LOAD_BATCH(RR, LAB, F)                                              \
    do {                                                                    \
        const int4 L0 = __ldg((const int4*)&labels[(RR)]);                  \
        const int4 L1 = __ldg((const int4*)&labels[(RR) + 4]);              \
        LAB[0] = L0.x; LAB[1] = L0.y; LAB[2] = L0.z; LAB[3] = L0.w;         \
        LAB[4] = L1.x; LAB[5] = L1.y; LAB[6] = L1.z; LAB[7] = L1.w;         \
        _Pragma("unroll")                                                   \
        for (int j = 0; j < 8; j++)                                         \
            if (LAB[j] != ign)                                              \
                F[j] = __ldcs(&feat[(size_t)((RR) + j) * A4 + tt]);         \
    } while (0)

#define RMW_BATCH(LAB, F)                                                   \
    do {                                                                    \
        _Pragma("unroll")                                                   \
        for (int j = 0; j < 8; j++) {                                       \
            if (LAB[j] != ign) {                                            \
                const int idx = LAB[j] * A4 + tt;                           \
                float4 s = ssum[idx];                                       \
                s.x += F[j].x; s.y += F[j].y; s.z += F[j].z; s.w += F[j].w; \
                ssum[idx] = s;                                              \
            }                                                               \
        }                                                                   \
        if (lane == 0) {                                                    \
            _Pragma("unroll")                                               \
            for (int j = 0; j < 2; j++) {                                   \
                const int jj = wgw * 2 + j;                                 \
                if (LAB[jj] != ign) scnt[warp * CPAD + LAB[jj]] += 1.f;     \
            }                                                               \
        }                                                                   \
    } while (0)

// One finalize unit = (class c, 16-float4 channel group agrp). 512 threads.
__device__ __forceinline__ void do_finalize_unit(
    int c, int agrp, float4* red, float* __restrict__ out)
{
    const int t    = threadIdx.x;
    const int a4   = t & 15;    // 0..15
    const int gp   = t >> 4;    // 0..31
    const int warp = t >> 5;    // 0..15
    const int lane = t & 31;

    __shared__ float wcnt[16];

    // per-class count: one load per thread (148 <= 512), warp-reduced
    {
        float cl = (t < GRID1) ? g_pcnts[t * NUM_C + c] : 0.f;
        #pragma unroll
        for (int o = 16; o > 0; o >>= 1)
            cl += __shfl_down_sync(0xFFFFFFFFu, cl, o);
        if (lane == 0) wcnt[warp] = cl;
    }

    const float4* ps = reinterpret_cast<const float4*>(g_psums);
    const size_t stride = (size_t)NUM_C * A4;
    const size_t off    = (size_t)c * A4 + agrp * 16 + a4;

    // partial-sum reduction: g = gp + 32*k, k = 0..3, + pred g = 128+gp
    const float4* base = ps + off + (size_t)gp * stride;
    float4 v0 = base[0];
    float4 v1 = base[(size_t)32 * stride];
    float4 v2 = base[(size_t)64 * stride];
    float4 v3 = base[(size_t)96 * stride];
    float4 v4 = make_float4(0.f, 0.f, 0.f, 0.f);
    if (gp < GRID1 - 128)
        v4 = base[(size_t)128 * stride];

    float4 acc;
    acc.x = (v0.x + v1.x) + (v2.x + v3.x) + v4.x;
    acc.y = (v0.y + v1.y) + (v2.y + v3.y) + v4.y;
    acc.z = (v0.z + v1.z) + (v2.z + v3.z) + v4.z;
    acc.w = (v0.w + v1.w) + (v2.w + v3.w) + v4.w;
    red[gp * 16 + a4] = acc;
    __syncthreads();

    // Fold 32 g-partitions -> 1.
    #pragma unroll
    for (int s = 16; s > 0; s >>= 1) {
        if (gp < s) {
            float4 a = red[gp * 16 + a4];
            float4 b = red[(gp + s) * 16 + a4];
            a.x += b.x; a.y += b.y; a.z += b.z; a.w += b.w;
            red[gp * 16 + a4] = a;
        }
        __syncthreads();
    }

    if (t < 16) {
        float cnt = 0.f;
        #pragma unroll
        for (int w = 0; w < 16; w++) cnt += wcnt[w];
        const float inv = 1.f / ((cnt == 0.f) ? 1.f : cnt);
        float4 sum = red[a4];
        float4 mean = make_float4(sum.x * inv, sum.y * inv, sum.z * inv, sum.w * inv);

        float4* out4 = reinterpret_cast<float4*>(out);
        const int oidx = c * A4 + agrp * 16 + a4;
        out4[oidx] = mean;                                         // mean (C, A)
        out4[NUM_C * A4 + oidx] = make_float4(cnt, cnt, cnt, cnt); // sum_weight
        if (t == 0 && agrp == 0)
            out[2 * NUM_C * NUM_A + c] = cnt;                      // class_dist (C,)
    }
    __syncthreads();  // red reused by a possible second unit
}

__global__ void __launch_bounds__(TPB1, 1) bars_fused_kernel(
    const float4* __restrict__ feat,
    const int*    __restrict__ labels,
    const int*    __restrict__ ignore_ptr,
    int N, float* __restrict__ out)
{
    extern __shared__ float4 smem4[];
    const int t    = threadIdx.x;
    const int wg   = t >> 7;        // warpgroup 0..3
    const int tt   = t & 127;       // float4 channel within warpgroup
    const int warp = t >> 5;        // 0..15
    const int wgw  = warp & 3;      // warp within warpgroup
    const int lane = t & 31;

    float4* ssum = smem4 + (size_t)wg * (NUM_C * A4);     // this wg's replica
    float*  scnt = (float*)(smem4 + SMEM_SSUM_F4);        // [16][CPAD]

    #pragma unroll
    for (int i = t; i < SMEM_SSUM_F4; i += TPB1)
        smem4[i] = make_float4(0.f, 0.f, 0.f, 0.f);
    if (t < 16 * CPAD) scnt[t] = 0.f;
    __syncthreads();

    const int ign   = *ignore_ptr;
    // rows per block rounded to 32 so warpgroup chunks stay 8-aligned
    const int rowsb = (((N + GRID1 - 1) / GRID1) + 31) & ~31;
    const int r0b   = blockIdx.x * rowsb;
    const int r1b   = min(r0b + rowsb, N);

    const int nb    = max(r1b - r0b, 0);
    int chunk = (nb + 3) >> 2;
    chunk = (chunk + 7) & ~7;                             // 8-aligned
    const int r0    = min(r0b + wg * chunk, r1b);
    const int r1    = min(r0 + chunk, r1b);

    const int nfull = (r1 - r0) >> 3;       // full 8-row batches

    int    labA[8], labB[8];
    float4 fA[8],   fB[8];

    if (nfull > 0) LOAD_BATCH(r0, labA, fA);

    int b = 0;
    // Pipelined main loop: prefetch batch b+1 before consuming batch b.
    for (; b + 2 < nfull; b += 2) {
        LOAD_BATCH(r0 + (b + 1) * 8, labB, fB);
        RMW_BATCH(labA, fA);
        LOAD_BATCH(r0 + (b + 2) * 8, labA, fA);
        RMW_BATCH(labB, fB);
    }
    if (nfull > 0) {
        if (b + 1 < nfull) {
            LOAD_BATCH(r0 + (b + 1) * 8, labB, fB);
            RMW_BATCH(labA, fA);
            RMW_BATCH(labB, fB);
        } else {
            RMW_BATCH(labA, fA);
        }
    }
    // scalar tail
    for (int r = r0 + nfull * 8; r < r1; r++) {
        const int lab = __ldg(&labels[r]);
        if (lab != ign) {
            float4 f = __ldcs(&feat[(size_t)r * A4 + tt]);
            const int idx = lab * A4 + tt;
            float4 s = ssum[idx];
            s.x += f.x; s.y += f.y; s.z += f.z; s.w += f.w;
            ssum[idx] = s;
            if (tt == 0) scnt[(wg * 4) * CPAD + lab] += 1.f;
        }
    }
    __syncthreads();

    // Reduce the 4 warpgroup replicas and store one slab per block.
    float4* pout = reinterpret_cast<float4*>(g_psums) + (size_t)blockIdx.x * NUM_C * A4;
    #pragma unroll
    for (int i = t; i < NUM_C * A4; i += TPB1) {
        float4 a  = smem4[i];
        float4 bb = smem4[i + NUM_C * A4];
        float4 c4 = smem4[i + 2 * NUM_C * A4];
        float4 d  = smem4[i + 3 * NUM_C * A4];
        a.x = (a.x + bb.x) + (c4.x + d.x);
        a.y = (a.y + bb.y) + (c4.y + d.y);
        a.z = (a.z + bb.z) + (c4.z + d.z);
        a.w = (a.w + bb.w) + (c4.w + d.w);
        pout[i] = a;
    }
    if (t < NUM_C) {
        float cl = 0.f;
        #pragma unroll
        for (int w = 0; w < 16; w++) cl += scnt[w * CPAD + t];
        g_pcnts[blockIdx.x * NUM_C + t] = cl;
    }
    __syncthreads();
    __threadfence();                       // release psums/pcnts
    if (t == 0) atomicAdd(&g_done, 1);

    // ---- gate: all 148 blocks are co-resident (one wave) -> spin is safe ----
    if (t == 0) {
        while (atomicAdd(&g_done, 0) < GRID1)
            __nanosleep(128);
    }
    __syncthreads();
    __threadfence();                       // acquire psums/pcnts

    // ---- finalize in-place: block b does unit b; blocks 0..3 also 148+b ----
    {
        const int u = blockIdx.x;
        do_finalize_unit(u >> 3, u & 7, smem4, out);
        if (blockIdx.x < NUNITS - GRID1) {
            const int u2 = GRID1 + blockIdx.x;
            do_finalize_unit(u2 >> 3, u2 & 7, smem4, out);
        }
    }

    // ---- counter self-reset so graph replays start from zero ----
    if (t == 0) {
        const int v = atomicAdd(&g_fin, 1);
        if (v == GRID1 - 1) {              // last block out resets both
            g_fin  = 0;
            g_done = 0;
            __threadfence();
        }
    }
}

extern "C" void kernel_launch(void* const* d_in, const int* in_sizes, int n_in,
                              void* d_out, int out_size)
{
    const float4* feat   = (const float4*)d_in[0];
    const int*    labels = (const int*)d_in[1];
    const int*    ign    = (const int*)d_in[2];
    float*        out    = (float*)d_out;

    const int N = in_sizes[0] / NUM_A;

    cudaFuncSetAttribute(bars_fused_kernel,
                         cudaFuncAttributeMaxDynamicSharedMemorySize, SMEM_BYTES);

    bars_fused_kernel<<<GRID1, TPB1, SMEM_BYTES>>>(feat, labels, ign, N, out);
}